// round 5
// baseline (speedup 1.0000x reference)
#include <cuda_runtime.h>
#include <cstdint>

#define B_ 2
#define D_ 2048
#define L_ 2048
#define R_ 128
#define N_ 16
#define E_ 160
#define BL_ 4096
#define NCH 16
#define LC 128
#define SPLITK 4
#define KC 512

// ---------------- static device scratch (no runtime allocation) ----------------
__device__ float g_UF[(size_t)BL_ * D_];        // u = silu(conv(hidden)), transposed to [bl][d]
__device__ float g_GS[(size_t)BL_ * D_];        // silu(gate) transposed to [bl][d]
__device__ float g_DELTA[(size_t)BL_ * D_];     // softplus(dt @ dt_w^T + dt_b), [bl][d]
__device__ float g_DT[(size_t)BL_ * R_];        // rmsnormed dt, [bl][r]
__device__ float g_BC[(size_t)BL_ * 32];        // per bl-row: B[0..16), C[16..32)
__device__ float g_SSMP[(size_t)SPLITK * BL_ * E_]; // split-K partials of x_proj
__device__ float g_PP[(size_t)NCH * B_ * D_];   // per-chunk sum of deltas
__device__ float g_ST[(size_t)NCH * B_ * N_ * D_]; // per-chunk final states -> init states

// ---------------- helpers ----------------
__device__ __forceinline__ float silu_f(float x) {
    return x / (1.f + __expf(-x));
}
__device__ __forceinline__ float softplus_f(float x) {
    return (x > 20.f) ? x : log1pf(__expf(x));
}

// ======================================================================
// Kernel 1: causal depthwise conv (K=4) + bias + SiLU on hidden, SiLU on
// gate, both transposed [B,D,L] -> [B*L, D] via smem tile transpose.
// ======================================================================
__global__ void conv_gate_kernel(const float* __restrict__ hidden,
                                 const float* __restrict__ gate,
                                 const float* __restrict__ conv_w,
                                 const float* __restrict__ conv_b)
{
    __shared__ float sh[32][36];   // hidden halo tile: rows=d, cols=l0-3..l0+31
    __shared__ float su[32][33];   // conv+silu result, rows=d, cols=l
    __shared__ float sg[32][33];   // silu(gate) result

    int tx = threadIdx.x;          // l index within tile
    int ty = threadIdx.y;          // d index within tile
    int l0 = blockIdx.x * 32;
    int d0 = blockIdx.y * 32;
    int b  = blockIdx.z;
    int d  = d0 + ty;

    const float* hrow = hidden + ((size_t)b * D_ + d) * L_;

    int lg = l0 - 3 + tx;
    sh[ty][tx] = (lg >= 0) ? hrow[lg] : 0.f;
    if (tx < 3) {
        sh[ty][32 + tx] = hrow[l0 + 29 + tx];   // cols l0+29..l0+31 (always in range)
    }
    __syncthreads();

    float w0 = conv_w[d * 4 + 0];
    float w1 = conv_w[d * 4 + 1];
    float w2 = conv_w[d * 4 + 2];
    float w3 = conv_w[d * 4 + 3];

    float acc = w0 * sh[ty][tx] + w1 * sh[ty][tx + 1]
              + w2 * sh[ty][tx + 2] + w3 * sh[ty][tx + 3] + conv_b[d];
    float uval = silu_f(acc);

    float gv = gate[((size_t)b * D_ + d) * L_ + l0 + tx];
    float gsv = silu_f(gv);

    su[ty][tx] = uval;
    sg[ty][tx] = gsv;
    __syncthreads();

    // transposed, coalesced store: thread (tx,ty) -> row l0+ty, col d0+tx
    size_t o = ((size_t)b * L_ + l0 + ty) * D_ + d0 + tx;
    g_UF[o] = su[tx][ty];
    g_GS[o] = sg[tx][ty];
}

// ======================================================================
// Kernel 2: x_proj GEMM (split-K partials).
// ssm[bl][e] = sum_d u[bl][d] * xproj_w[e][d];  M=4096, N=160, K=2048.
// BM=64, BN=160, BK=16, split-K=4 (each CTA owns K-chunk of 512).
// ======================================================================
__global__ void gemm1_kernel(const float* __restrict__ W)
{
    __shared__ float As[64][17];
    __shared__ float Bs[160][17];

    int tid = threadIdx.x;
    int m0 = blockIdx.x * 64;
    int kc = blockIdx.y;
    int kbase = kc * KC;

    float acc[8][5];
#pragma unroll
    for (int i = 0; i < 8; i++)
#pragma unroll
        for (int j = 0; j < 5; j++) acc[i][j] = 0.f;

    int tm = tid >> 5;        // 0..7
    int tn = tid & 31;        // 0..31

    int ar = tid >> 2;        // 0..63
    int ac = (tid & 3) * 4;   // 0,4,8,12

    for (int ks = 0; ks < KC; ks += 16) {
        float4 av = *(const float4*)&g_UF[(size_t)(m0 + ar) * D_ + kbase + ks + ac];
        As[ar][ac + 0] = av.x; As[ar][ac + 1] = av.y;
        As[ar][ac + 2] = av.z; As[ar][ac + 3] = av.w;
#pragma unroll
        for (int i = 0; i < 10; i++) {
            int idx = tid + 256 * i;
            int rr = idx >> 4, cc = idx & 15;
            Bs[rr][cc] = W[(size_t)rr * D_ + kbase + ks + cc];
        }
        __syncthreads();
#pragma unroll
        for (int k = 0; k < 16; k++) {
            float a[8], bb[5];
#pragma unroll
            for (int i = 0; i < 8; i++) a[i] = As[tm + 8 * i][k];
#pragma unroll
            for (int j = 0; j < 5; j++) bb[j] = Bs[tn + 32 * j][k];
#pragma unroll
            for (int i = 0; i < 8; i++)
#pragma unroll
                for (int j = 0; j < 5; j++) acc[i][j] = fmaf(a[i], bb[j], acc[i][j]);
        }
        __syncthreads();
    }

    float* outp = g_SSMP + (size_t)kc * BL_ * E_;
#pragma unroll
    for (int i = 0; i < 8; i++)
#pragma unroll
        for (int j = 0; j < 5; j++)
            outp[(size_t)(m0 + tm + 8 * i) * E_ + tn + 32 * j] = acc[i][j];
}

// ======================================================================
// Kernel 3: reduce split-K partials + 3-segment RMSNorm (dt:128, B:16, C:16)
// ======================================================================
__global__ void rmsnorm_kernel(const float* __restrict__ dt_ln_w,
                               const float* __restrict__ B_ln_w,
                               const float* __restrict__ C_ln_w)
{
    int row = blockIdx.x;
    int e = threadIdx.x;        // 0..159

    float v = 0.f;
#pragma unroll
    for (int p = 0; p < SPLITK; p++)
        v += g_SSMP[(size_t)p * BL_ * E_ + (size_t)row * E_ + e];

    __shared__ float sq[160];
    __shared__ float sums[3];
    sq[e] = v * v;
    __syncthreads();

    if (e == 0) { float s = 0.f; for (int i = 0; i < 128; i++) s += sq[i]; sums[0] = s; }
    if (e == 32) { float s = 0.f; for (int i = 128; i < 144; i++) s += sq[i]; sums[1] = s; }
    if (e == 64) { float s = 0.f; for (int i = 144; i < 160; i++) s += sq[i]; sums[2] = s; }
    __syncthreads();

    if (e < 128) {
        float o = v * rsqrtf(sums[0] * (1.f / 128.f) + 1e-6f) * dt_ln_w[e];
        g_DT[(size_t)row * R_ + e] = o;
    } else if (e < 144) {
        float o = v * rsqrtf(sums[1] * (1.f / 16.f) + 1e-6f) * B_ln_w[e - 128];
        g_BC[(size_t)row * 32 + (e - 128)] = o;
    } else {
        float o = v * rsqrtf(sums[2] * (1.f / 16.f) + 1e-6f) * C_ln_w[e - 144];
        g_BC[(size_t)row * 32 + (e - 128)] = o;
    }
}

// ======================================================================
// Kernel 4: delta GEMM + bias + softplus.
// delta[bl][d] = softplus(sum_r dt[bl][r]*dt_w[d][r] + dt_b[d]).
// M=4096, N=2048, K=128. BM=64, BN=128, BK=16.
// ======================================================================
__global__ void gemm2_kernel(const float* __restrict__ Wd,
                             const float* __restrict__ dt_b)
{
    __shared__ float As[64][17];
    __shared__ float Bs[128][17];

    int tid = threadIdx.x;
    int m0 = blockIdx.x * 64;
    int n0 = blockIdx.y * 128;

    float acc[8][4];
#pragma unroll
    for (int i = 0; i < 8; i++)
#pragma unroll
        for (int j = 0; j < 4; j++) acc[i][j] = 0.f;

    int tm = tid >> 5, tn = tid & 31;
    int ar = tid >> 2;
    int ac = (tid & 3) * 4;

    for (int ks = 0; ks < R_; ks += 16) {
        float4 av = *(const float4*)&g_DT[(size_t)(m0 + ar) * R_ + ks + ac];
        As[ar][ac + 0] = av.x; As[ar][ac + 1] = av.y;
        As[ar][ac + 2] = av.z; As[ar][ac + 3] = av.w;
#pragma unroll
        for (int i = 0; i < 2; i++) {
            int rr = ar + 64 * i;
            float4 bv = *(const float4*)&Wd[(size_t)(n0 + rr) * R_ + ks + ac];
            Bs[rr][ac + 0] = bv.x; Bs[rr][ac + 1] = bv.y;
            Bs[rr][ac + 2] = bv.z; Bs[rr][ac + 3] = bv.w;
        }
        __syncthreads();
#pragma unroll
        for (int k = 0; k < 16; k++) {
            float a[8], bb[4];
#pragma unroll
            for (int i = 0; i < 8; i++) a[i] = As[tm + 8 * i][k];
#pragma unroll
            for (int j = 0; j < 4; j++) bb[j] = Bs[tn + 32 * j][k];
#pragma unroll
            for (int i = 0; i < 8; i++)
#pragma unroll
                for (int j = 0; j < 4; j++) acc[i][j] = fmaf(a[i], bb[j], acc[i][j]);
        }
        __syncthreads();
    }

#pragma unroll
    for (int j = 0; j < 4; j++) {
        float bias = dt_b[n0 + tn + 32 * j];
#pragma unroll
        for (int i = 0; i < 8; i++) {
            float x = acc[i][j] + bias;
            g_DELTA[(size_t)(m0 + tm + 8 * i) * D_ + n0 + tn + 32 * j] = softplus_f(x);
        }
    }
}

// ======================================================================
// Kernel 5: scan phase A — per-chunk local scan from zero init.
// Records final state s[16] and chunk delta-sum (chunk decay = exp(A*dsum)).
// ======================================================================
__global__ void scanA_kernel(const float* __restrict__ A_log)
{
    int gid = blockIdx.x * 256 + threadIdx.x;
    int d = gid & (D_ - 1);
    int b = (gid >> 11) & (B_ - 1);
    int c = gid >> 12;

    float A[N_];
#pragma unroll
    for (int n = 0; n < N_; n++) A[n] = -__expf(A_log[d * N_ + n]);

    float s[N_];
#pragma unroll
    for (int n = 0; n < N_; n++) s[n] = 0.f;

    float dsum = 0.f;
    size_t base = ((size_t)b * L_ + (size_t)c * LC) * D_ + d;
    int bl0 = b * L_ + c * LC;

    for (int t = 0; t < LC; t++) {
        float uu = g_UF[base + (size_t)t * D_];
        float dl = g_DELTA[base + (size_t)t * D_];
        dsum += dl;
        const float4* Bp = (const float4*)&g_BC[(size_t)(bl0 + t) * 32];
        float4 b0 = Bp[0], b1 = Bp[1], b2 = Bp[2], b3 = Bp[3];
        float bv[N_] = {b0.x, b0.y, b0.z, b0.w, b1.x, b1.y, b1.z, b1.w,
                        b2.x, b2.y, b2.z, b2.w, b3.x, b3.y, b3.z, b3.w};
        float du = dl * uu;
#pragma unroll
        for (int n = 0; n < N_; n++)
            s[n] = __expf(dl * A[n]) * s[n] + du * bv[n];
    }

    g_PP[(size_t)(c * B_ + b) * D_ + d] = dsum;
#pragma unroll
    for (int n = 0; n < N_; n++)
        g_ST[((size_t)(c * B_ + b) * N_ + n) * D_ + d] = s[n];
}

// ======================================================================
// Kernel 6: scan phase B — sequential combine across 16 chunks.
// Replaces g_ST chunk-final states with chunk-initial states in place.
// ======================================================================
__global__ void scanB_kernel(const float* __restrict__ A_log)
{
    int gid = blockIdx.x * 256 + threadIdx.x;   // 0..4095
    int d = gid & (D_ - 1);
    int b = gid >> 11;

    float A[N_];
#pragma unroll
    for (int n = 0; n < N_; n++) A[n] = -__expf(A_log[d * N_ + n]);

    float carry[N_];
#pragma unroll
    for (int n = 0; n < N_; n++) carry[n] = 0.f;

    for (int c = 0; c < NCH; c++) {
        float ds = g_PP[(size_t)(c * B_ + b) * D_ + d];
#pragma unroll
        for (int n = 0; n < N_; n++) {
            size_t idx = ((size_t)(c * B_ + b) * N_ + n) * D_ + d;
            float sf = g_ST[idx];
            g_ST[idx] = carry[n];               // init state for chunk c
            carry[n] = __expf(A[n] * ds) * carry[n] + sf;
        }
    }
}

// ======================================================================
// Kernel 7: scan phase C — rescan with correct init, fused epilogue:
// out = (y + u*D_param) * silu(gate^T)
// ======================================================================
__global__ void scanC_kernel(const float* __restrict__ A_log,
                             const float* __restrict__ D_param,
                             float* __restrict__ out)
{
    int gid = blockIdx.x * 256 + threadIdx.x;
    int d = gid & (D_ - 1);
    int b = (gid >> 11) & (B_ - 1);
    int c = gid >> 12;

    float A[N_];
#pragma unroll
    for (int n = 0; n < N_; n++) A[n] = -__expf(A_log[d * N_ + n]);

    float s[N_];
#pragma unroll
    for (int n = 0; n < N_; n++)
        s[n] = g_ST[((size_t)(c * B_ + b) * N_ + n) * D_ + d];

    float Dp = D_param[d];
    size_t base = ((size_t)b * L_ + (size_t)c * LC) * D_ + d;
    int bl0 = b * L_ + c * LC;

    for (int t = 0; t < LC; t++) {
        float uu = g_UF[base + (size_t)t * D_];
        float dl = g_DELTA[base + (size_t)t * D_];
        const float4* Bp = (const float4*)&g_BC[(size_t)(bl0 + t) * 32];
        float4 b0 = Bp[0], b1 = Bp[1], b2 = Bp[2], b3 = Bp[3];
        float4 c0 = Bp[4], c1 = Bp[5], c2 = Bp[6], c3 = Bp[7];
        float bv[N_] = {b0.x, b0.y, b0.z, b0.w, b1.x, b1.y, b1.z, b1.w,
                        b2.x, b2.y, b2.z, b2.w, b3.x, b3.y, b3.z, b3.w};
        float cv[N_] = {c0.x, c0.y, c0.z, c0.w, c1.x, c1.y, c1.z, c1.w,
                        c2.x, c2.y, c2.z, c2.w, c3.x, c3.y, c3.z, c3.w};
        float du = dl * uu;
        float y = 0.f;
#pragma unroll
        for (int n = 0; n < N_; n++) {
            s[n] = __expf(dl * A[n]) * s[n] + du * bv[n];
            y = fmaf(s[n], cv[n], y);
        }
        float gs = g_GS[base + (size_t)t * D_];
        out[base + (size_t)t * D_] = (y + uu * Dp) * gs;
    }
}

// ======================================================================
extern "C" void kernel_launch(void* const* d_in, const int* in_sizes, int n_in,
                              void* d_out, int out_size)
{
    const float* hidden  = (const float*)d_in[0];
    const float* gate    = (const float*)d_in[1];
    const float* conv_w  = (const float*)d_in[2];
    const float* conv_b  = (const float*)d_in[3];
    const float* xproj_w = (const float*)d_in[4];
    const float* dt_w    = (const float*)d_in[5];
    const float* dt_b    = (const float*)d_in[6];
    const float* A_log   = (const float*)d_in[7];
    const float* D_param = (const float*)d_in[8];
    const float* dt_ln_w = (const float*)d_in[9];
    const float* B_ln_w  = (const float*)d_in[10];
    const float* C_ln_w  = (const float*)d_in[11];
    float* out = (float*)d_out;

    conv_gate_kernel<<<dim3(L_ / 32, D_ / 32, B_), dim3(32, 32)>>>(hidden, gate, conv_w, conv_b);
    gemm1_kernel<<<dim3(BL_ / 64, SPLITK), 256>>>(xproj_w);
    rmsnorm_kernel<<<BL_, 160>>>(dt_ln_w, B_ln_w, C_ln_w);
    gemm2_kernel<<<dim3(BL_ / 64, D_ / 128), 256>>>(dt_w, dt_b);
    scanA_kernel<<<NCH * B_ * D_ / 256, 256>>>(A_log);
    scanB_kernel<<<B_ * D_ / 256, 256>>>(A_log);
    scanC_kernel<<<NCH * B_ * D_ / 256, 256>>>(A_log, D_param, out);
}

// round 6
// speedup vs baseline: 1.0152x; 1.0152x over previous
#include <cuda_runtime.h>
#include <cstdint>

#define B_ 2
#define D_ 2048
#define L_ 2048
#define R_ 128
#define N_ 16
#define E_ 160
#define BL_ 4096
#define NCH 16
#define LC 128
#define SPLITK 4
#define KC 512

// ---------------- static device scratch (no runtime allocation) ----------------
__device__ float g_UF[(size_t)BL_ * D_];        // u = silu(conv(hidden)), transposed to [bl][d]
__device__ float g_GS[(size_t)BL_ * D_];        // silu(gate) transposed to [bl][d]
__device__ float g_DELTA[(size_t)BL_ * D_];     // softplus(dt @ dt_w^T + dt_b), [bl][d]
__device__ float g_DT[(size_t)BL_ * R_];        // rmsnormed dt, [bl][r]
__device__ float g_BC[(size_t)BL_ * 32];        // per bl-row: B[0..16), C[16..32)
__device__ float g_SSMP[(size_t)SPLITK * BL_ * E_]; // split-K partials of x_proj
__device__ float g_PP[(size_t)NCH * B_ * D_];   // per-chunk sum of deltas
__device__ float g_ST[(size_t)NCH * B_ * N_ * D_]; // per-chunk final states -> init states

// ---------------- helpers ----------------
__device__ __forceinline__ float silu_f(float x) {
    return x / (1.f + __expf(-x));
}
__device__ __forceinline__ float softplus_f(float x) {
    return (x > 20.f) ? x : log1pf(__expf(x));
}

// ======================================================================
// Kernel 1: causal depthwise conv (K=4) + bias + SiLU on hidden, SiLU on
// gate, both transposed [B,D,L] -> [B*L, D] via smem tile transpose.
// ======================================================================
__global__ void conv_gate_kernel(const float* __restrict__ hidden,
                                 const float* __restrict__ gate,
                                 const float* __restrict__ conv_w,
                                 const float* __restrict__ conv_b)
{
    __shared__ float sh[32][36];   // hidden halo tile: rows=d, cols=l0-3..l0+31
    __shared__ float su[32][33];   // conv+silu result, rows=d, cols=l
    __shared__ float sg[32][33];   // silu(gate) result

    int tx = threadIdx.x;          // l index within tile
    int ty = threadIdx.y;          // d index within tile
    int l0 = blockIdx.x * 32;
    int d0 = blockIdx.y * 32;
    int b  = blockIdx.z;
    int d  = d0 + ty;

    const float* hrow = hidden + ((size_t)b * D_ + d) * L_;

    int lg = l0 - 3 + tx;
    sh[ty][tx] = (lg >= 0) ? hrow[lg] : 0.f;
    if (tx < 3) {
        sh[ty][32 + tx] = hrow[l0 + 29 + tx];   // cols l0+29..l0+31 (always in range)
    }
    __syncthreads();

    float w0 = conv_w[d * 4 + 0];
    float w1 = conv_w[d * 4 + 1];
    float w2 = conv_w[d * 4 + 2];
    float w3 = conv_w[d * 4 + 3];

    float acc = w0 * sh[ty][tx] + w1 * sh[ty][tx + 1]
              + w2 * sh[ty][tx + 2] + w3 * sh[ty][tx + 3] + conv_b[d];
    float uval = silu_f(acc);

    float gv = gate[((size_t)b * D_ + d) * L_ + l0 + tx];
    float gsv = silu_f(gv);

    su[ty][tx] = uval;
    sg[ty][tx] = gsv;
    __syncthreads();

    // transposed, coalesced store: thread (tx,ty) -> row l0+ty, col d0+tx
    size_t o = ((size_t)b * L_ + l0 + ty) * D_ + d0 + tx;
    g_UF[o] = su[tx][ty];
    g_GS[o] = sg[tx][ty];
}

// ======================================================================
// Kernel 2: x_proj GEMM (split-K partials).
// ssm[bl][e] = sum_d u[bl][d] * xproj_w[e][d];  M=4096, N=160, K=2048.
// BM=64, BN=160, BK=16, split-K=4 (each CTA owns K-chunk of 512).
// ======================================================================
__global__ void gemm1_kernel(const float* __restrict__ W)
{
    __shared__ float As[64][17];
    __shared__ float Bs[160][17];

    int tid = threadIdx.x;
    int m0 = blockIdx.x * 64;
    int kc = blockIdx.y;
    int kbase = kc * KC;

    float acc[8][5];
#pragma unroll
    for (int i = 0; i < 8; i++)
#pragma unroll
        for (int j = 0; j < 5; j++) acc[i][j] = 0.f;

    int tm = tid >> 5;        // 0..7
    int tn = tid & 31;        // 0..31

    int ar = tid >> 2;        // 0..63
    int ac = (tid & 3) * 4;   // 0,4,8,12

    for (int ks = 0; ks < KC; ks += 16) {
        float4 av = *(const float4*)&g_UF[(size_t)(m0 + ar) * D_ + kbase + ks + ac];
        As[ar][ac + 0] = av.x; As[ar][ac + 1] = av.y;
        As[ar][ac + 2] = av.z; As[ar][ac + 3] = av.w;
#pragma unroll
        for (int i = 0; i < 10; i++) {
            int idx = tid + 256 * i;
            int rr = idx >> 4, cc = idx & 15;
            Bs[rr][cc] = W[(size_t)rr * D_ + kbase + ks + cc];
        }
        __syncthreads();
#pragma unroll
        for (int k = 0; k < 16; k++) {
            float a[8], bb[5];
#pragma unroll
            for (int i = 0; i < 8; i++) a[i] = As[tm + 8 * i][k];
#pragma unroll
            for (int j = 0; j < 5; j++) bb[j] = Bs[tn + 32 * j][k];
#pragma unroll
            for (int i = 0; i < 8; i++)
#pragma unroll
                for (int j = 0; j < 5; j++) acc[i][j] = fmaf(a[i], bb[j], acc[i][j]);
        }
        __syncthreads();
    }

    float* outp = g_SSMP + (size_t)kc * BL_ * E_;
#pragma unroll
    for (int i = 0; i < 8; i++)
#pragma unroll
        for (int j = 0; j < 5; j++)
            outp[(size_t)(m0 + tm + 8 * i) * E_ + tn + 32 * j] = acc[i][j];
}

// ======================================================================
// Kernel 3: reduce split-K partials + 3-segment RMSNorm (dt:128, B:16, C:16)
// ======================================================================
__global__ void rmsnorm_kernel(const float* __restrict__ dt_ln_w,
                               const float* __restrict__ B_ln_w,
                               const float* __restrict__ C_ln_w)
{
    int row = blockIdx.x;
    int e = threadIdx.x;        // 0..159

    float v = 0.f;
#pragma unroll
    for (int p = 0; p < SPLITK; p++)
        v += g_SSMP[(size_t)p * BL_ * E_ + (size_t)row * E_ + e];

    __shared__ float sq[160];
    __shared__ float sums[3];
    sq[e] = v * v;
    __syncthreads();

    if (e == 0) { float s = 0.f; for (int i = 0; i < 128; i++) s += sq[i]; sums[0] = s; }
    if (e == 32) { float s = 0.f; for (int i = 128; i < 144; i++) s += sq[i]; sums[1] = s; }
    if (e == 64) { float s = 0.f; for (int i = 144; i < 160; i++) s += sq[i]; sums[2] = s; }
    __syncthreads();

    if (e < 128) {
        float o = v * rsqrtf(sums[0] * (1.f / 128.f) + 1e-6f) * dt_ln_w[e];
        g_DT[(size_t)row * R_ + e] = o;
    } else if (e < 144) {
        float o = v * rsqrtf(sums[1] * (1.f / 16.f) + 1e-6f) * B_ln_w[e - 128];
        g_BC[(size_t)row * 32 + (e - 128)] = o;
    } else {
        float o = v * rsqrtf(sums[2] * (1.f / 16.f) + 1e-6f) * C_ln_w[e - 144];
        g_BC[(size_t)row * 32 + (e - 128)] = o;
    }
}

// ======================================================================
// Kernel 4: delta GEMM + bias + softplus.
// delta[bl][d] = softplus(sum_r dt[bl][r]*dt_w[d][r] + dt_b[d]).
// M=4096, N=2048, K=128. BM=64, BN=128, BK=16.
// ======================================================================
__global__ void gemm2_kernel(const float* __restrict__ Wd,
                             const float* __restrict__ dt_b)
{
    __shared__ float As[64][17];
    __shared__ float Bs[128][17];

    int tid = threadIdx.x;
    int m0 = blockIdx.x * 64;
    int n0 = blockIdx.y * 128;

    float acc[8][4];
#pragma unroll
    for (int i = 0; i < 8; i++)
#pragma unroll
        for (int j = 0; j < 4; j++) acc[i][j] = 0.f;

    int tm = tid >> 5, tn = tid & 31;
    int ar = tid >> 2;
    int ac = (tid & 3) * 4;

    for (int ks = 0; ks < R_; ks += 16) {
        float4 av = *(const float4*)&g_DT[(size_t)(m0 + ar) * R_ + ks + ac];
        As[ar][ac + 0] = av.x; As[ar][ac + 1] = av.y;
        As[ar][ac + 2] = av.z; As[ar][ac + 3] = av.w;
#pragma unroll
        for (int i = 0; i < 2; i++) {
            int rr = ar + 64 * i;
            float4 bv = *(const float4*)&Wd[(size_t)(n0 + rr) * R_ + ks + ac];
            Bs[rr][ac + 0] = bv.x; Bs[rr][ac + 1] = bv.y;
            Bs[rr][ac + 2] = bv.z; Bs[rr][ac + 3] = bv.w;
        }
        __syncthreads();
#pragma unroll
        for (int k = 0; k < 16; k++) {
            float a[8], bb[4];
#pragma unroll
            for (int i = 0; i < 8; i++) a[i] = As[tm + 8 * i][k];
#pragma unroll
            for (int j = 0; j < 4; j++) bb[j] = Bs[tn + 32 * j][k];
#pragma unroll
            for (int i = 0; i < 8; i++)
#pragma unroll
                for (int j = 0; j < 4; j++) acc[i][j] = fmaf(a[i], bb[j], acc[i][j]);
        }
        __syncthreads();
    }

#pragma unroll
    for (int j = 0; j < 4; j++) {
        float bias = dt_b[n0 + tn + 32 * j];
#pragma unroll
        for (int i = 0; i < 8; i++) {
            float x = acc[i][j] + bias;
            g_DELTA[(size_t)(m0 + tm + 8 * i) * D_ + n0 + tn + 32 * j] = softplus_f(x);
        }
    }
}

// ======================================================================
// Kernel 5: scan phase A — per-chunk local scan from zero init.
// Records final state s[16] and chunk delta-sum (chunk decay = exp(A*dsum)).
// ======================================================================
__global__ void scanA_kernel(const float* __restrict__ A_log)
{
    int gid = blockIdx.x * 256 + threadIdx.x;
    int d = gid & (D_ - 1);
    int b = (gid >> 11) & (B_ - 1);
    int c = gid >> 12;

    float A[N_];
#pragma unroll
    for (int n = 0; n < N_; n++) A[n] = -__expf(A_log[d * N_ + n]);

    float s[N_];
#pragma unroll
    for (int n = 0; n < N_; n++) s[n] = 0.f;

    float dsum = 0.f;
    size_t base = ((size_t)b * L_ + (size_t)c * LC) * D_ + d;
    int bl0 = b * L_ + c * LC;

    for (int t = 0; t < LC; t++) {
        float uu = g_UF[base + (size_t)t * D_];
        float dl = g_DELTA[base + (size_t)t * D_];
        dsum += dl;
        const float4* Bp = (const float4*)&g_BC[(size_t)(bl0 + t) * 32];
        float4 b0 = Bp[0], b1 = Bp[1], b2 = Bp[2], b3 = Bp[3];
        float bv[N_] = {b0.x, b0.y, b0.z, b0.w, b1.x, b1.y, b1.z, b1.w,
                        b2.x, b2.y, b2.z, b2.w, b3.x, b3.y, b3.z, b3.w};
        float du = dl * uu;
#pragma unroll
        for (int n = 0; n < N_; n++)
            s[n] = __expf(dl * A[n]) * s[n] + du * bv[n];
    }

    g_PP[(size_t)(c * B_ + b) * D_ + d] = dsum;
#pragma unroll
    for (int n = 0; n < N_; n++)
        g_ST[((size_t)(c * B_ + b) * N_ + n) * D_ + d] = s[n];
}

// ======================================================================
// Kernel 6: scan phase B — sequential combine across 16 chunks.
// Replaces g_ST chunk-final states with chunk-initial states in place.
// ======================================================================
__global__ void scanB_kernel(const float* __restrict__ A_log)
{
    int gid = blockIdx.x * 256 + threadIdx.x;   // 0..4095
    int d = gid & (D_ - 1);
    int b = gid >> 11;

    float A[N_];
#pragma unroll
    for (int n = 0; n < N_; n++) A[n] = -__expf(A_log[d * N_ + n]);

    float carry[N_];
#pragma unroll
    for (int n = 0; n < N_; n++) carry[n] = 0.f;

    for (int c = 0; c < NCH; c++) {
        float ds = g_PP[(size_t)(c * B_ + b) * D_ + d];
#pragma unroll
        for (int n = 0; n < N_; n++) {
            size_t idx = ((size_t)(c * B_ + b) * N_ + n) * D_ + d;
            float sf = g_ST[idx];
            g_ST[idx] = carry[n];               // init state for chunk c
            carry[n] = __expf(A[n] * ds) * carry[n] + sf;
        }
    }
}

// ======================================================================
// Kernel 7: scan phase C — rescan with correct init, fused epilogue:
// out = (y + u*D_param) * silu(gate^T)
// ======================================================================
__global__ void scanC_kernel(const float* __restrict__ A_log,
                             const float* __restrict__ D_param,
                             float* __restrict__ out)
{
    int gid = blockIdx.x * 256 + threadIdx.x;
    int d = gid & (D_ - 1);
    int b = (gid >> 11) & (B_ - 1);
    int c = gid >> 12;

    float A[N_];
#pragma unroll
    for (int n = 0; n < N_; n++) A[n] = -__expf(A_log[d * N_ + n]);

    float s[N_];
#pragma unroll
    for (int n = 0; n < N_; n++)
        s[n] = g_ST[((size_t)(c * B_ + b) * N_ + n) * D_ + d];

    float Dp = D_param[d];
    size_t base = ((size_t)b * L_ + (size_t)c * LC) * D_ + d;
    int bl0 = b * L_ + c * LC;

    for (int t = 0; t < LC; t++) {
        float uu = g_UF[base + (size_t)t * D_];
        float dl = g_DELTA[base + (size_t)t * D_];
        const float4* Bp = (const float4*)&g_BC[(size_t)(bl0 + t) * 32];
        float4 b0 = Bp[0], b1 = Bp[1], b2 = Bp[2], b3 = Bp[3];
        float4 c0 = Bp[4], c1 = Bp[5], c2 = Bp[6], c3 = Bp[7];
        float bv[N_] = {b0.x, b0.y, b0.z, b0.w, b1.x, b1.y, b1.z, b1.w,
                        b2.x, b2.y, b2.z, b2.w, b3.x, b3.y, b3.z, b3.w};
        float cv[N_] = {c0.x, c0.y, c0.z, c0.w, c1.x, c1.y, c1.z, c1.w,
                        c2.x, c2.y, c2.z, c2.w, c3.x, c3.y, c3.z, c3.w};
        float du = dl * uu;
        float y = 0.f;
#pragma unroll
        for (int n = 0; n < N_; n++) {
            s[n] = __expf(dl * A[n]) * s[n] + du * bv[n];
            y = fmaf(s[n], cv[n], y);
        }
        float gs = g_GS[base + (size_t)t * D_];
        out[base + (size_t)t * D_] = (y + uu * Dp) * gs;
    }
}

// ======================================================================
extern "C" void kernel_launch(void* const* d_in, const int* in_sizes, int n_in,
                              void* d_out, int out_size)
{
    const float* hidden  = (const float*)d_in[0];
    const float* gate    = (const float*)d_in[1];
    const float* conv_w  = (const float*)d_in[2];
    const float* conv_b  = (const float*)d_in[3];
    const float* xproj_w = (const float*)d_in[4];
    const float* dt_w    = (const float*)d_in[5];
    const float* dt_b    = (const float*)d_in[6];
    const float* A_log   = (const float*)d_in[7];
    const float* D_param = (const float*)d_in[8];
    const float* dt_ln_w = (const float*)d_in[9];
    const float* B_ln_w  = (const float*)d_in[10];
    const float* C_ln_w  = (const float*)d_in[11];
    float* out = (float*)d_out;

    conv_gate_kernel<<<dim3(L_ / 32, D_ / 32, B_), dim3(32, 32)>>>(hidden, gate, conv_w, conv_b);
    gemm1_kernel<<<dim3(BL_ / 64, SPLITK), 256>>>(xproj_w);
    rmsnorm_kernel<<<BL_, 160>>>(dt_ln_w, B_ln_w, C_ln_w);
    gemm2_kernel<<<dim3(BL_ / 64, D_ / 128), 256>>>(dt_w, dt_b);
    scanA_kernel<<<NCH * B_ * D_ / 256, 256>>>(A_log);
    scanB_kernel<<<B_ * D_ / 256, 256>>>(A_log);
    scanC_kernel<<<NCH * B_ * D_ / 256, 256>>>(A_log, D_param, out);
}

// round 7
// speedup vs baseline: 1.0189x; 1.0036x over previous
#include <cuda_runtime.h>
#include <cstdint>

#define B_ 2
#define D_ 2048
#define L_ 2048
#define R_ 128
#define N_ 16
#define E_ 160
#define BL_ 4096
#define NCH 16
#define LC 128
#define SPLITK 4
#define KC 512

// ---------------- static device scratch (no runtime allocation) ----------------
__device__ float g_UF[(size_t)BL_ * D_];        // u = silu(conv(hidden)), transposed to [bl][d]
__device__ float g_GS[(size_t)BL_ * D_];        // silu(gate) transposed to [bl][d]
__device__ float g_DELTA[(size_t)BL_ * D_];     // softplus(dt @ dt_w^T + dt_b), [bl][d]
__device__ float g_DT[(size_t)BL_ * R_];        // rmsnormed dt, [bl][r]
__device__ float g_BC[(size_t)BL_ * 32];        // per bl-row: B[0..16), C[16..32)
__device__ float g_SSMP[(size_t)SPLITK * BL_ * E_]; // split-K partials of x_proj
__device__ float g_PP[(size_t)NCH * B_ * D_];   // per-chunk sum of deltas
__device__ float g_ST[(size_t)NCH * B_ * N_ * D_]; // per-chunk final states -> init states

// ---------------- helpers ----------------
__device__ __forceinline__ float silu_f(float x) {
    return x / (1.f + __expf(-x));
}
__device__ __forceinline__ float softplus_f(float x) {
    return (x > 20.f) ? x : log1pf(__expf(x));
}

// ======================================================================
// Kernel 1: causal depthwise conv (K=4) + bias + SiLU on hidden, SiLU on
// gate, both transposed [B,D,L] -> [B*L, D] via smem tile transpose.
// ======================================================================
__global__ void conv_gate_kernel(const float* __restrict__ hidden,
                                 const float* __restrict__ gate,
                                 const float* __restrict__ conv_w,
                                 const float* __restrict__ conv_b)
{
    __shared__ float sh[32][36];   // hidden halo tile: rows=d, cols=l0-3..l0+31
    __shared__ float su[32][33];   // conv+silu result, rows=d, cols=l
    __shared__ float sg[32][33];   // silu(gate) result

    int tx = threadIdx.x;          // l index within tile
    int ty = threadIdx.y;          // d index within tile
    int l0 = blockIdx.x * 32;
    int d0 = blockIdx.y * 32;
    int b  = blockIdx.z;
    int d  = d0 + ty;

    const float* hrow = hidden + ((size_t)b * D_ + d) * L_;

    int lg = l0 - 3 + tx;
    sh[ty][tx] = (lg >= 0) ? hrow[lg] : 0.f;
    if (tx < 3) {
        sh[ty][32 + tx] = hrow[l0 + 29 + tx];   // cols l0+29..l0+31 (always in range)
    }
    __syncthreads();

    float w0 = conv_w[d * 4 + 0];
    float w1 = conv_w[d * 4 + 1];
    float w2 = conv_w[d * 4 + 2];
    float w3 = conv_w[d * 4 + 3];

    float acc = w0 * sh[ty][tx] + w1 * sh[ty][tx + 1]
              + w2 * sh[ty][tx + 2] + w3 * sh[ty][tx + 3] + conv_b[d];
    float uval = silu_f(acc);

    float gv = gate[((size_t)b * D_ + d) * L_ + l0 + tx];
    float gsv = silu_f(gv);

    su[ty][tx] = uval;
    sg[ty][tx] = gsv;
    __syncthreads();

    // transposed, coalesced store: thread (tx,ty) -> row l0+ty, col d0+tx
    size_t o = ((size_t)b * L_ + l0 + ty) * D_ + d0 + tx;
    g_UF[o] = su[tx][ty];
    g_GS[o] = sg[tx][ty];
}

// ======================================================================
// Kernel 2: x_proj GEMM (split-K partials).
// ssm[bl][e] = sum_d u[bl][d] * xproj_w[e][d];  M=4096, N=160, K=2048.
// BM=64, BN=160, BK=16, split-K=4 (each CTA owns K-chunk of 512).
// ======================================================================
__global__ void gemm1_kernel(const float* __restrict__ W)
{
    __shared__ float As[64][17];
    __shared__ float Bs[160][17];

    int tid = threadIdx.x;
    int m0 = blockIdx.x * 64;
    int kc = blockIdx.y;
    int kbase = kc * KC;

    float acc[8][5];
#pragma unroll
    for (int i = 0; i < 8; i++)
#pragma unroll
        for (int j = 0; j < 5; j++) acc[i][j] = 0.f;

    int tm = tid >> 5;        // 0..7
    int tn = tid & 31;        // 0..31

    int ar = tid >> 2;        // 0..63
    int ac = (tid & 3) * 4;   // 0,4,8,12

    for (int ks = 0; ks < KC; ks += 16) {
        float4 av = *(const float4*)&g_UF[(size_t)(m0 + ar) * D_ + kbase + ks + ac];
        As[ar][ac + 0] = av.x; As[ar][ac + 1] = av.y;
        As[ar][ac + 2] = av.z; As[ar][ac + 3] = av.w;
#pragma unroll
        for (int i = 0; i < 10; i++) {
            int idx = tid + 256 * i;
            int rr = idx >> 4, cc = idx & 15;
            Bs[rr][cc] = W[(size_t)rr * D_ + kbase + ks + cc];
        }
        __syncthreads();
#pragma unroll
        for (int k = 0; k < 16; k++) {
            float a[8], bb[5];
#pragma unroll
            for (int i = 0; i < 8; i++) a[i] = As[tm + 8 * i][k];
#pragma unroll
            for (int j = 0; j < 5; j++) bb[j] = Bs[tn + 32 * j][k];
#pragma unroll
            for (int i = 0; i < 8; i++)
#pragma unroll
                for (int j = 0; j < 5; j++) acc[i][j] = fmaf(a[i], bb[j], acc[i][j]);
        }
        __syncthreads();
    }

    float* outp = g_SSMP + (size_t)kc * BL_ * E_;
#pragma unroll
    for (int i = 0; i < 8; i++)
#pragma unroll
        for (int j = 0; j < 5; j++)
            outp[(size_t)(m0 + tm + 8 * i) * E_ + tn + 32 * j] = acc[i][j];
}

// ======================================================================
// Kernel 3: reduce split-K partials + 3-segment RMSNorm (dt:128, B:16, C:16)
// ======================================================================
__global__ void rmsnorm_kernel(const float* __restrict__ dt_ln_w,
                               const float* __restrict__ B_ln_w,
                               const float* __restrict__ C_ln_w)
{
    int row = blockIdx.x;
    int e = threadIdx.x;        // 0..159

    float v = 0.f;
#pragma unroll
    for (int p = 0; p < SPLITK; p++)
        v += g_SSMP[(size_t)p * BL_ * E_ + (size_t)row * E_ + e];

    __shared__ float sq[160];
    __shared__ float sums[3];
    sq[e] = v * v;
    __syncthreads();

    if (e == 0) { float s = 0.f; for (int i = 0; i < 128; i++) s += sq[i]; sums[0] = s; }
    if (e == 32) { float s = 0.f; for (int i = 128; i < 144; i++) s += sq[i]; sums[1] = s; }
    if (e == 64) { float s = 0.f; for (int i = 144; i < 160; i++) s += sq[i]; sums[2] = s; }
    __syncthreads();

    if (e < 128) {
        float o = v * rsqrtf(sums[0] * (1.f / 128.f) + 1e-6f) * dt_ln_w[e];
        g_DT[(size_t)row * R_ + e] = o;
    } else if (e < 144) {
        float o = v * rsqrtf(sums[1] * (1.f / 16.f) + 1e-6f) * B_ln_w[e - 128];
        g_BC[(size_t)row * 32 + (e - 128)] = o;
    } else {
        float o = v * rsqrtf(sums[2] * (1.f / 16.f) + 1e-6f) * C_ln_w[e - 144];
        g_BC[(size_t)row * 32 + (e - 128)] = o;
    }
}

// ======================================================================
// Kernel 4: delta GEMM + bias + softplus.
// delta[bl][d] = softplus(sum_r dt[bl][r]*dt_w[d][r] + dt_b[d]).
// M=4096, N=2048, K=128. BM=64, BN=128, BK=16.
// ======================================================================
__global__ void gemm2_kernel(const float* __restrict__ Wd,
                             const float* __restrict__ dt_b)
{
    __shared__ float As[64][17];
    __shared__ float Bs[128][17];

    int tid = threadIdx.x;
    int m0 = blockIdx.x * 64;
    int n0 = blockIdx.y * 128;

    float acc[8][4];
#pragma unroll
    for (int i = 0; i < 8; i++)
#pragma unroll
        for (int j = 0; j < 4; j++) acc[i][j] = 0.f;

    int tm = tid >> 5, tn = tid & 31;
    int ar = tid >> 2;
    int ac = (tid & 3) * 4;

    for (int ks = 0; ks < R_; ks += 16) {
        float4 av = *(const float4*)&g_DT[(size_t)(m0 + ar) * R_ + ks + ac];
        As[ar][ac + 0] = av.x; As[ar][ac + 1] = av.y;
        As[ar][ac + 2] = av.z; As[ar][ac + 3] = av.w;
#pragma unroll
        for (int i = 0; i < 2; i++) {
            int rr = ar + 64 * i;
            float4 bv = *(const float4*)&Wd[(size_t)(n0 + rr) * R_ + ks + ac];
            Bs[rr][ac + 0] = bv.x; Bs[rr][ac + 1] = bv.y;
            Bs[rr][ac + 2] = bv.z; Bs[rr][ac + 3] = bv.w;
        }
        __syncthreads();
#pragma unroll
        for (int k = 0; k < 16; k++) {
            float a[8], bb[4];
#pragma unroll
            for (int i = 0; i < 8; i++) a[i] = As[tm + 8 * i][k];
#pragma unroll
            for (int j = 0; j < 4; j++) bb[j] = Bs[tn + 32 * j][k];
#pragma unroll
            for (int i = 0; i < 8; i++)
#pragma unroll
                for (int j = 0; j < 4; j++) acc[i][j] = fmaf(a[i], bb[j], acc[i][j]);
        }
        __syncthreads();
    }

#pragma unroll
    for (int j = 0; j < 4; j++) {
        float bias = dt_b[n0 + tn + 32 * j];
#pragma unroll
        for (int i = 0; i < 8; i++) {
            float x = acc[i][j] + bias;
            g_DELTA[(size_t)(m0 + tm + 8 * i) * D_ + n0 + tn + 32 * j] = softplus_f(x);
        }
    }
}

// ======================================================================
// Kernel 5: scan phase A — per-chunk local scan from zero init.
// Records final state s[16] and chunk delta-sum (chunk decay = exp(A*dsum)).
// ======================================================================
__global__ void scanA_kernel(const float* __restrict__ A_log)
{
    int gid = blockIdx.x * 256 + threadIdx.x;
    int d = gid & (D_ - 1);
    int b = (gid >> 11) & (B_ - 1);
    int c = gid >> 12;

    float A[N_];
#pragma unroll
    for (int n = 0; n < N_; n++) A[n] = -__expf(A_log[d * N_ + n]);

    float s[N_];
#pragma unroll
    for (int n = 0; n < N_; n++) s[n] = 0.f;

    float dsum = 0.f;
    size_t base = ((size_t)b * L_ + (size_t)c * LC) * D_ + d;
    int bl0 = b * L_ + c * LC;

    for (int t = 0; t < LC; t++) {
        float uu = g_UF[base + (size_t)t * D_];
        float dl = g_DELTA[base + (size_t)t * D_];
        dsum += dl;
        const float4* Bp = (const float4*)&g_BC[(size_t)(bl0 + t) * 32];
        float4 b0 = Bp[0], b1 = Bp[1], b2 = Bp[2], b3 = Bp[3];
        float bv[N_] = {b0.x, b0.y, b0.z, b0.w, b1.x, b1.y, b1.z, b1.w,
                        b2.x, b2.y, b2.z, b2.w, b3.x, b3.y, b3.z, b3.w};
        float du = dl * uu;
#pragma unroll
        for (int n = 0; n < N_; n++)
            s[n] = __expf(dl * A[n]) * s[n] + du * bv[n];
    }

    g_PP[(size_t)(c * B_ + b) * D_ + d] = dsum;
#pragma unroll
    for (int n = 0; n < N_; n++)
        g_ST[((size_t)(c * B_ + b) * N_ + n) * D_ + d] = s[n];
}

// ======================================================================
// Kernel 6: scan phase B — sequential combine across 16 chunks.
// Replaces g_ST chunk-final states with chunk-initial states in place.
// ======================================================================
__global__ void scanB_kernel(const float* __restrict__ A_log)
{
    int gid = blockIdx.x * 256 + threadIdx.x;   // 0..4095
    int d = gid & (D_ - 1);
    int b = gid >> 11;

    float A[N_];
#pragma unroll
    for (int n = 0; n < N_; n++) A[n] = -__expf(A_log[d * N_ + n]);

    float carry[N_];
#pragma unroll
    for (int n = 0; n < N_; n++) carry[n] = 0.f;

    for (int c = 0; c < NCH; c++) {
        float ds = g_PP[(size_t)(c * B_ + b) * D_ + d];
#pragma unroll
        for (int n = 0; n < N_; n++) {
            size_t idx = ((size_t)(c * B_ + b) * N_ + n) * D_ + d;
            float sf = g_ST[idx];
            g_ST[idx] = carry[n];               // init state for chunk c
            carry[n] = __expf(A[n] * ds) * carry[n] + sf;
        }
    }
}

// ======================================================================
// Kernel 7: scan phase C — rescan with correct init, fused epilogue:
// out = (y + u*D_param) * silu(gate^T)
// ======================================================================
__global__ void scanC_kernel(const float* __restrict__ A_log,
                             const float* __restrict__ D_param,
                             float* __restrict__ out)
{
    int gid = blockIdx.x * 256 + threadIdx.x;
    int d = gid & (D_ - 1);
    int b = (gid >> 11) & (B_ - 1);
    int c = gid >> 12;

    float A[N_];
#pragma unroll
    for (int n = 0; n < N_; n++) A[n] = -__expf(A_log[d * N_ + n]);

    float s[N_];
#pragma unroll
    for (int n = 0; n < N_; n++)
        s[n] = g_ST[((size_t)(c * B_ + b) * N_ + n) * D_ + d];

    float Dp = D_param[d];
    size_t base = ((size_t)b * L_ + (size_t)c * LC) * D_ + d;
    int bl0 = b * L_ + c * LC;

    for (int t = 0; t < LC; t++) {
        float uu = g_UF[base + (size_t)t * D_];
        float dl = g_DELTA[base + (size_t)t * D_];
        const float4* Bp = (const float4*)&g_BC[(size_t)(bl0 + t) * 32];
        float4 b0 = Bp[0], b1 = Bp[1], b2 = Bp[2], b3 = Bp[3];
        float4 c0 = Bp[4], c1 = Bp[5], c2 = Bp[6], c3 = Bp[7];
        float bv[N_] = {b0.x, b0.y, b0.z, b0.w, b1.x, b1.y, b1.z, b1.w,
                        b2.x, b2.y, b2.z, b2.w, b3.x, b3.y, b3.z, b3.w};
        float cv[N_] = {c0.x, c0.y, c0.z, c0.w, c1.x, c1.y, c1.z, c1.w,
                        c2.x, c2.y, c2.z, c2.w, c3.x, c3.y, c3.z, c3.w};
        float du = dl * uu;
        float y = 0.f;
#pragma unroll
        for (int n = 0; n < N_; n++) {
            s[n] = __expf(dl * A[n]) * s[n] + du * bv[n];
            y = fmaf(s[n], cv[n], y);
        }
        float gs = g_GS[base + (size_t)t * D_];
        out[base + (size_t)t * D_] = (y + uu * Dp) * gs;
    }
}

// ======================================================================
extern "C" void kernel_launch(void* const* d_in, const int* in_sizes, int n_in,
                              void* d_out, int out_size)
{
    const float* hidden  = (const float*)d_in[0];
    const float* gate    = (const float*)d_in[1];
    const float* conv_w  = (const float*)d_in[2];
    const float* conv_b  = (const float*)d_in[3];
    const float* xproj_w = (const float*)d_in[4];
    const float* dt_w    = (const float*)d_in[5];
    const float* dt_b    = (const float*)d_in[6];
    const float* A_log   = (const float*)d_in[7];
    const float* D_param = (const float*)d_in[8];
    const float* dt_ln_w = (const float*)d_in[9];
    const float* B_ln_w  = (const float*)d_in[10];
    const float* C_ln_w  = (const float*)d_in[11];
    float* out = (float*)d_out;

    conv_gate_kernel<<<dim3(L_ / 32, D_ / 32, B_), dim3(32, 32)>>>(hidden, gate, conv_w, conv_b);
    gemm1_kernel<<<dim3(BL_ / 64, SPLITK), 256>>>(xproj_w);
    rmsnorm_kernel<<<BL_, 160>>>(dt_ln_w, B_ln_w, C_ln_w);
    gemm2_kernel<<<dim3(BL_ / 64, D_ / 128), 256>>>(dt_w, dt_b);
    scanA_kernel<<<NCH * B_ * D_ / 256, 256>>>(A_log);
    scanB_kernel<<<B_ * D_ / 256, 256>>>(A_log);
    scanC_kernel<<<NCH * B_ * D_ / 256, 256>>>(A_log, D_param, out);
}